// round 3
// baseline (speedup 1.0000x reference)
#include <cuda_runtime.h>
#include <math.h>

#define HH 128
#define WW 128
#define HW 16384
#define BB 2

// ---------------- scratch (device globals: allocation-free) ----------------
__device__ float g_ef  [BB*196*HW];   // concat(extra_feat, flow1, flow2)
__device__ float g_h1  [BB*64*HW];    // h1 / h3
__device__ float g_h2  [BB*64*HW];    // h2
__device__ float g_off [BB*288*HW];   // final offsets (y,x interleaved, torchvision layout)
__device__ float g_mask[BB*144*HW];   // sigmoid mask
__device__ float g_xt  [BB*128*HW];   // x transposed to [b][g][y][x][cpg=8]

// ---------------- elementwise prep ----------------
__global__ __launch_bounds__(256) void concat_ef_k(
    const float* __restrict__ ef, const float* __restrict__ f1, const float* __restrict__ f2)
{
    int i = blockIdx.x*256 + threadIdx.x;
    if (i >= BB*196*HW) return;
    int pix = i % HW;
    int c = (i / HW) % 196;
    int b = i / (196*HW);
    float v;
    if (c < 192)      v = ef[((size_t)b*192 + c)*HW + pix];
    else if (c < 194) v = f1[((size_t)b*2 + (c-192))*HW + pix];
    else              v = f2[((size_t)b*2 + (c-194))*HW + pix];
    g_ef[i] = v;
}

__global__ __launch_bounds__(256) void transp_x_k(const float* __restrict__ x)
{
    int i = blockIdx.x*256 + threadIdx.x;   // i = ((b*16+g)*HW + pix)*8 + cc
    if (i >= BB*128*HW) return;
    int cc   = i & 7;
    int rest = i >> 3;
    int pix  = rest % HW;
    int g    = (rest / HW) % 16;
    int b    = rest / (16*HW);
    g_xt[i] = x[((size_t)(b*128 + g*8 + cc))*HW + pix];
}

// ---------------- generic 3x3 conv, stride 1, pad 1 ----------------
// Block: 256 threads; output tile 32x32 pixels x 8 output channels.
// Thread: 2x2 pixels x 8 Cout = 32 accumulators.
// EPI=0: leaky(0.1) -> out.  EPI=1: conv4 epilogue -> g_off/g_mask.
template<int EPI>
__global__ __launch_bounds__(256) void conv3x3_k(
    const float* __restrict__ in, const float* __restrict__ w,
    const float* __restrict__ bias, float* __restrict__ out,
    int Cin, int Cout,
    const float* __restrict__ flow1, const float* __restrict__ flow2)
{
    __shared__ float s_in[8][34*34];   // 8 cin x (32+2)^2, zero-padded
    __shared__ float s_w[8*9*8];       // [(c*9+k)*8 + o]

    int tw  = blockIdx.x;        // tile x (0..3)
    int th  = blockIdx.y & 3;    // tile y (0..3)
    int b   = blockIdx.y >> 2;   // batch
    int oc0 = blockIdx.z * 8;
    int t   = threadIdx.x;
    int tx  = t & 15, ty = t >> 4;

    float accs[32];
#pragma unroll
    for (int i = 0; i < 32; i++) accs[i] = 0.f;

    const float* inb = in + (size_t)b*Cin*HW;
    int nchunk = (Cin + 7) >> 3;

    for (int cc = 0; cc < nchunk; cc++) {
        int cbase = cc << 3;
        // load input tile chunk (zero pad for borders + channel overrun)
        for (int i = t; i < 8*34*34; i += 256) {
            int c   = i / 1156;
            int rem = i - c*1156;
            int r   = rem / 34;
            int col = rem - r*34;
            int gy = (th<<5) + r - 1;
            int gx = (tw<<5) + col - 1;
            int ch = cbase + c;
            float v = 0.f;
            if (ch < Cin && (unsigned)gy < HH && (unsigned)gx < WW)
                v = inb[(size_t)ch*HW + gy*WW + gx];
            s_in[c][rem] = v;
        }
        // load weights chunk; i == (c*9+k)*8 + o by construction
        for (int i = t; i < 576; i += 256) {
            int o  = i & 7;
            int kk = (i >> 3) % 9;
            int c  = i / 72;
            int ch = cbase + c;
            float v = 0.f;
            if (ch < Cin) v = w[((size_t)(oc0+o)*Cin + ch)*9 + kk];
            s_w[i] = v;
        }
        __syncthreads();

#pragma unroll
        for (int c = 0; c < 8; c++) {
#pragma unroll
            for (int ky = 0; ky < 3; ky++) {
                int r0 = (ty*2 + ky)*34 + tx*2;
#pragma unroll
                for (int kx = 0; kx < 3; kx++) {
                    float x00 = s_in[c][r0 + kx];
                    float x01 = s_in[c][r0 + kx + 1];
                    float x10 = s_in[c][r0 + 34 + kx];
                    float x11 = s_in[c][r0 + 34 + kx + 1];
                    const float4* wp = (const float4*)&s_w[(c*9 + ky*3 + kx)*8];
                    float4 w0 = wp[0], w1 = wp[1];
                    float wv[8] = {w0.x,w0.y,w0.z,w0.w,w1.x,w1.y,w1.z,w1.w};
#pragma unroll
                    for (int o = 0; o < 8; o++) {
                        accs[o]      = fmaf(x00, wv[o], accs[o]);
                        accs[8 + o]  = fmaf(x01, wv[o], accs[8 + o]);
                        accs[16 + o] = fmaf(x10, wv[o], accs[16 + o]);
                        accs[24 + o] = fmaf(x11, wv[o], accs[24 + o]);
                    }
                }
            }
        }
        __syncthreads();
    }

    int px0 = (tw<<5) + tx*2;
    int py0 = (th<<5) + ty*2;
#pragma unroll
    for (int o = 0; o < 8; o++) {
        float bv = bias[oc0 + o];
#pragma unroll
        for (int i = 0; i < 4; i++) {
            float v = accs[i*8 + o] + bv;
            int py = py0 + (i >> 1), px = px0 + (i & 1);
            int pix = py*WW + px;
            if (EPI == 0) {
                v = v >= 0.f ? v : 0.1f*v;
                out[((size_t)b*Cout + oc0 + o)*HW + pix] = v;
            } else {
                int c = oc0 + o;   // 0..431
                if (c < 288) {
                    // offset = 10*tanh(v) + tiled flipped flow
                    const float* fl = (c < 144) ? flow1 : flow2;
                    float add = fl[((size_t)b*2 + (1 - (c & 1)))*HW + pix];
                    g_off[((size_t)b*288 + c)*HW + pix] = 10.f*tanhf(v) + add;
                } else {
                    g_mask[((size_t)b*144 + (c - 288))*HW + pix] = 1.f/(1.f + expf(-v));
                }
            }
        }
    }
}

// ---------------- modulated deformable conv (G=16, cpg=8, K=9) ----------------
// Block: 256 threads, 64 consecutive pixels (one half-row), all 64 Cout.
// Per group: sample 64px x 72(cpg*K) values into smem, then 64x64x72 GEMM.
__global__ __launch_bounds__(256) void dcn_k(
    const float* __restrict__ w, const float* __restrict__ bias, float* __restrict__ out)
{
    __shared__ float s_val[72][64];
    __shared__ float s_w[72][64];

    int blk = blockIdx.x;
    int b   = blk >> 8;            // / (HW/64) = 256 tiles per batch
    int p0  = (blk & 255) << 6;    // linear pixel base (half a row)
    int t   = threadIdx.x;
    int o4  = (t & 15) << 2;       // 4 output channels
    int pb  = (t >> 4) << 2;       // 4 pixels

    float accs[16];
#pragma unroll
    for (int i = 0; i < 16; i++) accs[i] = 0.f;

    const float* offb = g_off  + (size_t)b*288*HW;
    const float* mb   = g_mask + (size_t)b*144*HW;
    const float* xb   = g_xt   + (size_t)b*128*HW;

    for (int g = 0; g < 16; g++) {
        // weights: s_w[c*9+k][o] = dcn_w[o][g*8+c][k]
        for (int i = t; i < 72*64; i += 256) {
            int o = i & 63;
            int j = i >> 6;
            s_w[j][o] = w[(size_t)o*1152 + (g*8 + j/9)*9 + (j % 9)];
        }
        // sampling: 576 (pixel,k) tasks, 8 channels each (channels-last float4x2)
        for (int task = t; task < 576; task += 256) {
            int k   = task >> 6;
            int p   = task & 63;
            int pix = p0 + p;
            int y   = pix >> 7;
            int x   = pix & 127;
            int ch  = g*9 + k;
            float oy = offb[(size_t)(ch*2)    *HW + pix];
            float ox = offb[(size_t)(ch*2 + 1)*HW + pix];
            float m  = mb  [(size_t)ch*HW + pix];
            float py = (float)(y + (k/3) - 1) + oy;
            float px = (float)(x + (k%3) - 1) + ox;
            float fy = floorf(py), fx = floorf(px);
            float wy = py - fy, wx = px - fx;
            int y0 = (int)fy, x0 = (int)fx;
            float w00 = (1.f - wy)*(1.f - wx)*m;
            float w01 = (1.f - wy)*wx*m;
            float w10 = wy*(1.f - wx)*m;
            float w11 = wy*wx*m;
            const float* gb = xb + (size_t)g*(HW*8);
            float4 lo = {0,0,0,0}, hi = {0,0,0,0};
            auto corner = [&](int yy, int xx, float wt) {
                if ((unsigned)yy < HH && (unsigned)xx < WW) {
                    const float4* cp = (const float4*)(gb + ((size_t)(yy*WW + xx) << 3));
                    float4 a = cp[0], c2 = cp[1];
                    lo.x = fmaf(wt, a.x, lo.x);  lo.y = fmaf(wt, a.y, lo.y);
                    lo.z = fmaf(wt, a.z, lo.z);  lo.w = fmaf(wt, a.w, lo.w);
                    hi.x = fmaf(wt, c2.x, hi.x); hi.y = fmaf(wt, c2.y, hi.y);
                    hi.z = fmaf(wt, c2.z, hi.z); hi.w = fmaf(wt, c2.w, hi.w);
                }
            };
            corner(y0,     x0,     w00);
            corner(y0,     x0 + 1, w01);
            corner(y0 + 1, x0,     w10);
            corner(y0 + 1, x0 + 1, w11);
            s_val[0*9 + k][p] = lo.x;  s_val[1*9 + k][p] = lo.y;
            s_val[2*9 + k][p] = lo.z;  s_val[3*9 + k][p] = lo.w;
            s_val[4*9 + k][p] = hi.x;  s_val[5*9 + k][p] = hi.y;
            s_val[6*9 + k][p] = hi.z;  s_val[7*9 + k][p] = hi.w;
        }
        __syncthreads();

#pragma unroll 8
        for (int j = 0; j < 72; j++) {
            float4 wv = *(const float4*)&s_w[j][o4];
            float4 vv = *(const float4*)&s_val[j][pb];
            accs[0]  = fmaf(wv.x, vv.x, accs[0]);
            accs[1]  = fmaf(wv.x, vv.y, accs[1]);
            accs[2]  = fmaf(wv.x, vv.z, accs[2]);
            accs[3]  = fmaf(wv.x, vv.w, accs[3]);
            accs[4]  = fmaf(wv.y, vv.x, accs[4]);
            accs[5]  = fmaf(wv.y, vv.y, accs[5]);
            accs[6]  = fmaf(wv.y, vv.z, accs[6]);
            accs[7]  = fmaf(wv.y, vv.w, accs[7]);
            accs[8]  = fmaf(wv.z, vv.x, accs[8]);
            accs[9]  = fmaf(wv.z, vv.y, accs[9]);
            accs[10] = fmaf(wv.z, vv.z, accs[10]);
            accs[11] = fmaf(wv.z, vv.w, accs[11]);
            accs[12] = fmaf(wv.w, vv.x, accs[12]);
            accs[13] = fmaf(wv.w, vv.y, accs[13]);
            accs[14] = fmaf(wv.w, vv.z, accs[14]);
            accs[15] = fmaf(wv.w, vv.w, accs[15]);
        }
        __syncthreads();
    }

#pragma unroll
    for (int oi = 0; oi < 4; oi++) {
        float bv = bias[o4 + oi];
#pragma unroll
        for (int pi = 0; pi < 4; pi++)
            out[((size_t)b*64 + o4 + oi)*HW + p0 + pb + pi] = accs[oi*4 + pi] + bv;
    }
}

// ---------------- launch ----------------
extern "C" void kernel_launch(void* const* d_in, const int* in_sizes, int n_in,
                              void* d_out, int out_size)
{
    const float* x   = (const float*)d_in[0];
    const float* exf = (const float*)d_in[1];
    const float* f1  = (const float*)d_in[2];
    const float* f2  = (const float*)d_in[3];
    const float* w1  = (const float*)d_in[4];
    const float* b1  = (const float*)d_in[5];
    const float* w2  = (const float*)d_in[6];
    const float* b2  = (const float*)d_in[7];
    const float* w3  = (const float*)d_in[8];
    const float* b3  = (const float*)d_in[9];
    const float* w4  = (const float*)d_in[10];
    const float* b4  = (const float*)d_in[11];
    const float* dw  = (const float*)d_in[12];
    const float* db  = (const float*)d_in[13];
    float* out = (float*)d_out;

    float *p_ef, *p_h1, *p_h2;
    cudaGetSymbolAddress((void**)&p_ef, g_ef);
    cudaGetSymbolAddress((void**)&p_h1, g_h1);
    cudaGetSymbolAddress((void**)&p_h2, g_h2);

    concat_ef_k<<<(BB*196*HW + 255)/256, 256>>>(exf, f1, f2);
    transp_x_k <<<(BB*128*HW + 255)/256, 256>>>(x);

    conv3x3_k<0><<<dim3(4, 4*BB, 8),  256>>>(p_ef, w1, b1, p_h1, 196, 64, nullptr, nullptr);
    conv3x3_k<0><<<dim3(4, 4*BB, 8),  256>>>(p_h1, w2, b2, p_h2,  64, 64, nullptr, nullptr);
    conv3x3_k<0><<<dim3(4, 4*BB, 8),  256>>>(p_h2, w3, b3, p_h1,  64, 64, nullptr, nullptr);
    conv3x3_k<1><<<dim3(4, 4*BB, 54), 256>>>(p_h1, w4, b4, nullptr, 64, 432, f1, f2);

    dcn_k<<<BB*(HW/64), 256>>>(dw, db, out);
}

// round 4
// speedup vs baseline: 1.1906x; 1.1906x over previous
#include <cuda_runtime.h>
#include <math.h>

#define HH 128
#define WW 128
#define HW 16384
#define BB 2

// ---------------- scratch (device globals: allocation-free) ----------------
__device__ float g_ef  [BB*196*HW];      // concat(extra_feat, flow1, flow2)
__device__ float g_h1  [BB*64*HW];       // h1 / h3
__device__ float g_h2  [BB*64*HW];       // h2
__device__ float g_off [BB*288*HW];      // final offsets (torchvision layout)
__device__ float g_mask[BB*144*HW];      // sigmoid mask
__device__ float g_xt  [BB*128*HW];      // x transposed to [b][g][y][x][cpg=8]
__device__ float g_wt  [16*72*64];       // dcn weights transposed [g][j=c*9+k][o]
__device__ float g_part[4*BB*64*HW];     // per-quad partial sums

// ---------------- elementwise prep ----------------
__global__ __launch_bounds__(256) void concat_ef_k(
    const float* __restrict__ ef, const float* __restrict__ f1, const float* __restrict__ f2)
{
    int i = blockIdx.x*256 + threadIdx.x;
    if (i >= BB*196*HW) return;
    int pix = i % HW;
    int c = (i / HW) % 196;
    int b = i / (196*HW);
    float v;
    if (c < 192)      v = ef[((size_t)b*192 + c)*HW + pix];
    else if (c < 194) v = f1[((size_t)b*2 + (c-192))*HW + pix];
    else              v = f2[((size_t)b*2 + (c-194))*HW + pix];
    g_ef[i] = v;
}

__global__ __launch_bounds__(256) void transp_x_k(const float* __restrict__ x)
{
    int i = blockIdx.x*256 + threadIdx.x;   // i = ((b*16+g)*HW + pix)*8 + cc
    if (i >= BB*128*HW) return;
    int cc   = i & 7;
    int rest = i >> 3;
    int pix  = rest % HW;
    int g    = (rest / HW) % 16;
    int b    = rest / (16*HW);
    g_xt[i] = x[((size_t)(b*128 + g*8 + cc))*HW + pix];
}

__global__ __launch_bounds__(256) void transp_w_k(const float* __restrict__ w)
{
    int i = blockIdx.x*256 + threadIdx.x;   // i = (g*72 + j)*64 + o
    if (i >= 16*72*64) return;
    int o = i & 63;
    int j = (i >> 6) % 72;
    int g = i / (72*64);
    g_wt[i] = w[(size_t)o*1152 + (g*8 + j/9)*9 + (j % 9)];
}

// ---------------- generic 3x3 conv, stride 1, pad 1 ----------------
// Block: 256 threads; output tile 32(w)x16(h) pixels x 8 output channels.
// Thread: 2 horizontal px x 8 Cout = 16 accumulators.
// EPI=0: leaky(0.1) -> out.  EPI=1: conv4 epilogue -> g_off/g_mask.
template<int EPI>
__global__ __launch_bounds__(256) void conv3x3_k(
    const float* __restrict__ in, const float* __restrict__ w,
    const float* __restrict__ bias, float* __restrict__ out,
    int Cin, int Cout,
    const float* __restrict__ flow1, const float* __restrict__ flow2)
{
    __shared__ float s_in[8][18*34];   // 8 cin x (16+2)x(32+2), zero-padded
    __shared__ float s_w[8*9*8];       // [(c*9+k)*8 + o]

    int tw  = blockIdx.x;          // tile x (0..3)
    int th  = blockIdx.y & 7;      // tile y (0..7)
    int b   = blockIdx.y >> 3;     // batch
    int oc0 = blockIdx.z * 8;
    int t   = threadIdx.x;
    int tx  = t & 15, ty = t >> 4; // tx 0..15 (2px each), ty 0..15

    float accs[16];
#pragma unroll
    for (int i = 0; i < 16; i++) accs[i] = 0.f;

    const float* inb = in + (size_t)b*Cin*HW;
    int nchunk = (Cin + 7) >> 3;

    for (int cc = 0; cc < nchunk; cc++) {
        int cbase = cc << 3;
        // input tile chunk (zero pad borders + channel overrun)
        for (int i = t; i < 8*18*34; i += 256) {
            int c   = i / 612;
            int rem = i - c*612;
            int r   = rem / 34;
            int col = rem - r*34;
            int gy = (th<<4) + r - 1;
            int gx = (tw<<5) + col - 1;
            int ch = cbase + c;
            float v = 0.f;
            if (ch < Cin && (unsigned)gy < HH && (unsigned)gx < WW)
                v = inb[(size_t)ch*HW + gy*WW + gx];
            s_in[c][rem] = v;
        }
        // weights chunk; i == (c*9+k)*8 + o
        for (int i = t; i < 576; i += 256) {
            int o  = i & 7;
            int kk = (i >> 3) % 9;
            int c  = i / 72;
            int ch = cbase + c;
            float v = 0.f;
            if (ch < Cin) v = w[((size_t)(oc0+o)*Cin + ch)*9 + kk];
            s_w[i] = v;
        }
        __syncthreads();

#pragma unroll
        for (int c = 0; c < 8; c++) {
#pragma unroll
            for (int ky = 0; ky < 3; ky++) {
                int r0 = (ty + ky)*34 + tx*2;
                float v0 = s_in[c][r0];
                float v1 = s_in[c][r0 + 1];
                float v2 = s_in[c][r0 + 2];
                float v3 = s_in[c][r0 + 3];
                float vv[4] = {v0, v1, v2, v3};
#pragma unroll
                for (int kx = 0; kx < 3; kx++) {
                    const float4* wp = (const float4*)&s_w[(c*9 + ky*3 + kx)*8];
                    float4 w0 = wp[0], w1 = wp[1];
                    float wv[8] = {w0.x,w0.y,w0.z,w0.w,w1.x,w1.y,w1.z,w1.w};
                    float xa = vv[kx], xb = vv[kx + 1];
#pragma unroll
                    for (int o = 0; o < 8; o++) {
                        accs[o]     = fmaf(xa, wv[o], accs[o]);
                        accs[8 + o] = fmaf(xb, wv[o], accs[8 + o]);
                    }
                }
            }
        }
        __syncthreads();
    }

    int px0 = (tw<<5) + tx*2;
    int py  = (th<<4) + ty;
    int pixbase = py*WW + px0;
#pragma unroll
    for (int o = 0; o < 8; o++) {
        float bv = bias[oc0 + o];
#pragma unroll
        for (int i = 0; i < 2; i++) {
            float v = accs[i*8 + o] + bv;
            int pix = pixbase + i;
            if (EPI == 0) {
                v = v >= 0.f ? v : 0.1f*v;
                out[((size_t)b*Cout + oc0 + o)*HW + pix] = v;
            } else {
                int c = oc0 + o;   // 0..431
                if (c < 288) {
                    const float* fl = (c < 144) ? flow1 : flow2;
                    float add = fl[((size_t)b*2 + (1 - (c & 1)))*HW + pix];
                    g_off[((size_t)b*288 + c)*HW + pix] = 10.f*tanhf(v) + add;
                } else {
                    g_mask[((size_t)b*144 + (c - 288))*HW + pix] = 1.f/(1.f + expf(-v));
                }
            }
        }
    }
}

// ---------------- modulated deformable conv, 4-way group split ----------------
// Grid: (256 pixel-tiles, BB, 4 quads). Block: 256 threads, 64 px, 4 groups
// accumulated in registers; partial result per quad to g_part.
__global__ __launch_bounds__(256) void dcn4_k()
{
    __shared__ float s_val[72][64];
    __shared__ float s_w[72][64];

    int p0 = blockIdx.x << 6;      // pixel base (half a row)
    int b  = blockIdx.y;
    int q  = blockIdx.z;           // group quad
    int t  = threadIdx.x;
    int o4 = (t & 15) << 2;        // 4 output channels
    int pb = (t >> 4) << 2;        // 4 pixels

    float accs[16];
#pragma unroll
    for (int i = 0; i < 16; i++) accs[i] = 0.f;

    const float* offb = g_off  + (size_t)b*288*HW;
    const float* mb   = g_mask + (size_t)b*144*HW;
    const float* xb   = g_xt   + (size_t)b*128*HW;

    for (int gi = 0; gi < 4; gi++) {
        int g = q*4 + gi;
        // weights: coalesced float4 copy from pre-transposed g_wt
        {
            const float4* src = (const float4*)(g_wt + (size_t)g*4608);
            float4* dst = (float4*)&s_w[0][0];
            for (int i = t; i < 1152; i += 256) dst[i] = src[i];
        }
        // sampling: 576 (k,pixel) tasks, 8 channels each, clamped unconditional loads
#pragma unroll
        for (int rep = 0; rep < 3; rep++) {
            int task = t + (rep << 8);
            if (task < 576) {
                int k   = task >> 6;
                int p   = task & 63;
                int pix = p0 + p;
                int y   = pix >> 7;
                int x   = pix & 127;
                int ch  = g*9 + k;
                float oy = offb[(size_t)(2*ch)    *HW + pix];
                float ox = offb[(size_t)(2*ch + 1)*HW + pix];
                float m  = mb  [(size_t)ch*HW + pix];
                float py = (float)(y + (k/3) - 1) + oy;
                float px = (float)(x + (k%3) - 1) + ox;
                float fy = floorf(py), fx = floorf(px);
                float wy = py - fy, wx = px - fx;
                int y0 = (int)fy,  x0 = (int)fx;
                int y1 = y0 + 1,   x1 = x0 + 1;
                float vy0 = ((unsigned)y0 < HH) ? 1.f : 0.f;
                float vy1 = ((unsigned)y1 < HH) ? 1.f : 0.f;
                float vx0 = ((unsigned)x0 < WW) ? 1.f : 0.f;
                float vx1 = ((unsigned)x1 < WW) ? 1.f : 0.f;
                int y0c = min(max(y0, 0), HH-1), y1c = min(max(y1, 0), HH-1);
                int x0c = min(max(x0, 0), WW-1), x1c = min(max(x1, 0), WW-1);
                float w00 = (1.f-wy)*(1.f-wx)*m*vy0*vx0;
                float w01 = (1.f-wy)*wx      *m*vy0*vx1;
                float w10 = wy*(1.f-wx)      *m*vy1*vx0;
                float w11 = wy*wx            *m*vy1*vx1;
                const float* gb = xb + (size_t)g*(HW*8);
                const float4* c00 = (const float4*)(gb + ((size_t)(y0c*WW + x0c) << 3));
                const float4* c01 = (const float4*)(gb + ((size_t)(y0c*WW + x1c) << 3));
                const float4* c10 = (const float4*)(gb + ((size_t)(y1c*WW + x0c) << 3));
                const float4* c11 = (const float4*)(gb + ((size_t)(y1c*WW + x1c) << 3));
                float4 a0 = c00[0], a1 = c00[1];
                float4 b0 = c01[0], b1 = c01[1];
                float4 d0 = c10[0], d1 = c10[1];
                float4 e0 = c11[0], e1 = c11[1];
                float lo0 = w00*a0.x + w01*b0.x + w10*d0.x + w11*e0.x;
                float lo1 = w00*a0.y + w01*b0.y + w10*d0.y + w11*e0.y;
                float lo2 = w00*a0.z + w01*b0.z + w10*d0.z + w11*e0.z;
                float lo3 = w00*a0.w + w01*b0.w + w10*d0.w + w11*e0.w;
                float hi0 = w00*a1.x + w01*b1.x + w10*d1.x + w11*e1.x;
                float hi1 = w00*a1.y + w01*b1.y + w10*d1.y + w11*e1.y;
                float hi2 = w00*a1.z + w01*b1.z + w10*d1.z + w11*e1.z;
                float hi3 = w00*a1.w + w01*b1.w + w10*d1.w + w11*e1.w;
                s_val[0*9 + k][p] = lo0;  s_val[1*9 + k][p] = lo1;
                s_val[2*9 + k][p] = lo2;  s_val[3*9 + k][p] = lo3;
                s_val[4*9 + k][p] = hi0;  s_val[5*9 + k][p] = hi1;
                s_val[6*9 + k][p] = hi2;  s_val[7*9 + k][p] = hi3;
            }
        }
        __syncthreads();

#pragma unroll 8
        for (int j = 0; j < 72; j++) {
            float4 wv = *(const float4*)&s_w[j][o4];
            float4 vv = *(const float4*)&s_val[j][pb];
            accs[0]  = fmaf(wv.x, vv.x, accs[0]);
            accs[1]  = fmaf(wv.x, vv.y, accs[1]);
            accs[2]  = fmaf(wv.x, vv.z, accs[2]);
            accs[3]  = fmaf(wv.x, vv.w, accs[3]);
            accs[4]  = fmaf(wv.y, vv.x, accs[4]);
            accs[5]  = fmaf(wv.y, vv.y, accs[5]);
            accs[6]  = fmaf(wv.y, vv.z, accs[6]);
            accs[7]  = fmaf(wv.y, vv.w, accs[7]);
            accs[8]  = fmaf(wv.z, vv.x, accs[8]);
            accs[9]  = fmaf(wv.z, vv.y, accs[9]);
            accs[10] = fmaf(wv.z, vv.z, accs[10]);
            accs[11] = fmaf(wv.z, vv.w, accs[11]);
            accs[12] = fmaf(wv.w, vv.x, accs[12]);
            accs[13] = fmaf(wv.w, vv.y, accs[13]);
            accs[14] = fmaf(wv.w, vv.z, accs[14]);
            accs[15] = fmaf(wv.w, vv.w, accs[15]);
        }
        __syncthreads();
    }

    float* pout = g_part + (((size_t)(q*BB + b))*64)*HW;
#pragma unroll
    for (int oi = 0; oi < 4; oi++)
#pragma unroll
        for (int pi = 0; pi < 4; pi++)
            pout[(size_t)(o4 + oi)*HW + p0 + pb + pi] = accs[oi*4 + pi];
}

// ---------------- reduce 4 quad-partials + bias ----------------
__global__ __launch_bounds__(256) void reduce_k(const float* __restrict__ bias,
                                                float* __restrict__ out)
{
    int i = blockIdx.x*256 + threadIdx.x;     // over BB*64*HW
    if (i >= BB*64*HW) return;
    int pix = i & (HW - 1);
    int c   = (i >> 14) & 63;
    int b   = i >> 20;
    float s = bias[c];
#pragma unroll
    for (int q = 0; q < 4; q++)
        s += g_part[(((size_t)(q*BB + b))*64 + c)*HW + pix];
    out[i] = s;
}

// ---------------- launch ----------------
extern "C" void kernel_launch(void* const* d_in, const int* in_sizes, int n_in,
                              void* d_out, int out_size)
{
    const float* x   = (const float*)d_in[0];
    const float* exf = (const float*)d_in[1];
    const float* f1  = (const float*)d_in[2];
    const float* f2  = (const float*)d_in[3];
    const float* w1  = (const float*)d_in[4];
    const float* b1  = (const float*)d_in[5];
    const float* w2  = (const float*)d_in[6];
    const float* b2  = (const float*)d_in[7];
    const float* w3  = (const float*)d_in[8];
    const float* b3  = (const float*)d_in[9];
    const float* w4  = (const float*)d_in[10];
    const float* b4  = (const float*)d_in[11];
    const float* dw  = (const float*)d_in[12];
    const float* db  = (const float*)d_in[13];
    float* out = (float*)d_out;

    float *p_ef, *p_h1, *p_h2;
    cudaGetSymbolAddress((void**)&p_ef, g_ef);
    cudaGetSymbolAddress((void**)&p_h1, g_h1);
    cudaGetSymbolAddress((void**)&p_h2, g_h2);

    concat_ef_k<<<(BB*196*HW + 255)/256, 256>>>(exf, f1, f2);
    transp_x_k <<<(BB*128*HW + 255)/256, 256>>>(x);
    transp_w_k <<<(16*72*64 + 255)/256, 256>>>(dw);

    conv3x3_k<0><<<dim3(4, 16, 8),  256>>>(p_ef, w1, b1, p_h1, 196, 64, nullptr, nullptr);
    conv3x3_k<0><<<dim3(4, 16, 8),  256>>>(p_h1, w2, b2, p_h2,  64, 64, nullptr, nullptr);
    conv3x3_k<0><<<dim3(4, 16, 8),  256>>>(p_h2, w3, b3, p_h1,  64, 64, nullptr, nullptr);
    conv3x3_k<1><<<dim3(4, 16, 54), 256>>>(p_h1, w4, b4, nullptr, 64, 432, f1, f2);

    dcn4_k<<<dim3(256, BB, 4), 256>>>();

    reduce_k<<<(BB*64*HW + 255)/256, 256>>>(db, out);
}

// round 5
// speedup vs baseline: 1.1912x; 1.0005x over previous
#include <cuda_runtime.h>
#include <math.h>

#define HH 128
#define WW 128
#define HW 16384
#define BB 2

// ---------------- scratch (device globals: allocation-free) ----------------
__device__ float g_ef  [BB*196*HW];      // concat(extra_feat, flow1, flow2)
__device__ float g_h1  [BB*64*HW];       // h1 / h3
__device__ float g_h2  [BB*64*HW];       // h2
__device__ float g_off [BB*288*HW];      // final offsets (torchvision layout)
__device__ float g_mask[BB*144*HW];      // sigmoid mask
__device__ float g_xt  [BB*128*HW];      // x transposed to [b][g][y][x][cpg=8]
__device__ float g_wt  [16*72*64];       // dcn weights transposed [g][j=c*9+k][o]
__device__ float g_part[4*BB*64*HW];     // per-quad partial sums

// ---------------- elementwise prep ----------------
__global__ __launch_bounds__(256) void concat_ef_k(
    const float* __restrict__ ef, const float* __restrict__ f1, const float* __restrict__ f2)
{
    int i = blockIdx.x*256 + threadIdx.x;
    if (i >= BB*196*HW) return;
    int pix = i % HW;
    int c = (i / HW) % 196;
    int b = i / (196*HW);
    float v;
    if (c < 192)      v = ef[((size_t)b*192 + c)*HW + pix];
    else if (c < 194) v = f1[((size_t)b*2 + (c-192))*HW + pix];
    else              v = f2[((size_t)b*2 + (c-194))*HW + pix];
    g_ef[i] = v;
}

__global__ __launch_bounds__(256) void transp_x_k(const float* __restrict__ x)
{
    int i = blockIdx.x*256 + threadIdx.x;   // i = ((b*16+g)*HW + pix)*8 + cc
    if (i >= BB*128*HW) return;
    int cc   = i & 7;
    int rest = i >> 3;
    int pix  = rest % HW;
    int g    = (rest / HW) % 16;
    int b    = rest / (16*HW);
    g_xt[i] = x[((size_t)(b*128 + g*8 + cc))*HW + pix];
}

__global__ __launch_bounds__(256) void transp_w_k(const float* __restrict__ w)
{
    int i = blockIdx.x*256 + threadIdx.x;   // i = (g*72 + j)*64 + o
    if (i >= 16*72*64) return;
    int o = i & 63;
    int j = (i >> 6) % 72;
    int g = i / (72*64);
    g_wt[i] = w[(size_t)o*1152 + (g*8 + j/9)*9 + (j % 9)];
}

// ---------------- generic 3x3 conv, stride 1, pad 1 ----------------
// Block: 256 threads; output tile 32(w)x16(h) pixels x 8 output channels.
// Thread: 2 horizontal px x 8 Cout = 16 accumulators.
// EPI=0: leaky(0.1) -> out.  EPI=1: conv4 epilogue -> g_off/g_mask.
template<int EPI>
__global__ __launch_bounds__(256) void conv3x3_k(
    const float* __restrict__ in, const float* __restrict__ w,
    const float* __restrict__ bias, float* __restrict__ out,
    int Cin, int Cout,
    const float* __restrict__ flow1, const float* __restrict__ flow2)
{
    __shared__ float s_in[8][18*34];   // 8 cin x (16+2)x(32+2), zero-padded
    __shared__ float s_w[8*9*8];       // [(c*9+k)*8 + o]

    int tw  = blockIdx.x;          // tile x (0..3)
    int th  = blockIdx.y & 7;      // tile y (0..7)
    int b   = blockIdx.y >> 3;     // batch
    int oc0 = blockIdx.z * 8;
    int t   = threadIdx.x;
    int tx  = t & 15, ty = t >> 4; // tx 0..15 (2px each), ty 0..15

    float accs[16];
#pragma unroll
    for (int i = 0; i < 16; i++) accs[i] = 0.f;

    const float* inb = in + (size_t)b*Cin*HW;
    int nchunk = (Cin + 7) >> 3;

    for (int cc = 0; cc < nchunk; cc++) {
        int cbase = cc << 3;
        // input tile chunk (zero pad borders + channel overrun)
        for (int i = t; i < 8*18*34; i += 256) {
            int c   = i / 612;
            int rem = i - c*612;
            int r   = rem / 34;
            int col = rem - r*34;
            int gy = (th<<4) + r - 1;
            int gx = (tw<<5) + col - 1;
            int ch = cbase + c;
            float v = 0.f;
            if (ch < Cin && (unsigned)gy < HH && (unsigned)gx < WW)
                v = inb[(size_t)ch*HW + gy*WW + gx];
            s_in[c][rem] = v;
        }
        // weights chunk; i == (c*9+k)*8 + o
        for (int i = t; i < 576; i += 256) {
            int o  = i & 7;
            int kk = (i >> 3) % 9;
            int c  = i / 72;
            int ch = cbase + c;
            float v = 0.f;
            if (ch < Cin) v = w[((size_t)(oc0+o)*Cin + ch)*9 + kk];
            s_w[i] = v;
        }
        __syncthreads();

#pragma unroll
        for (int c = 0; c < 8; c++) {
#pragma unroll
            for (int ky = 0; ky < 3; ky++) {
                int r0 = (ty + ky)*34 + tx*2;
                float v0 = s_in[c][r0];
                float v1 = s_in[c][r0 + 1];
                float v2 = s_in[c][r0 + 2];
                float v3 = s_in[c][r0 + 3];
                float vv[4] = {v0, v1, v2, v3};
#pragma unroll
                for (int kx = 0; kx < 3; kx++) {
                    const float4* wp = (const float4*)&s_w[(c*9 + ky*3 + kx)*8];
                    float4 w0 = wp[0], w1 = wp[1];
                    float wv[8] = {w0.x,w0.y,w0.z,w0.w,w1.x,w1.y,w1.z,w1.w};
                    float xa = vv[kx], xb = vv[kx + 1];
#pragma unroll
                    for (int o = 0; o < 8; o++) {
                        accs[o]     = fmaf(xa, wv[o], accs[o]);
                        accs[8 + o] = fmaf(xb, wv[o], accs[8 + o]);
                    }
                }
            }
        }
        __syncthreads();
    }

    int px0 = (tw<<5) + tx*2;
    int py  = (th<<4) + ty;
    int pixbase = py*WW + px0;
#pragma unroll
    for (int o = 0; o < 8; o++) {
        float bv = bias[oc0 + o];
#pragma unroll
        for (int i = 0; i < 2; i++) {
            float v = accs[i*8 + o] + bv;
            int pix = pixbase + i;
            if (EPI == 0) {
                v = v >= 0.f ? v : 0.1f*v;
                out[((size_t)b*Cout + oc0 + o)*HW + pix] = v;
            } else {
                int c = oc0 + o;   // 0..431
                if (c < 288) {
                    const float* fl = (c < 144) ? flow1 : flow2;
                    float add = fl[((size_t)b*2 + (1 - (c & 1)))*HW + pix];
                    g_off[((size_t)b*288 + c)*HW + pix] = 10.f*tanhf(v) + add;
                } else {
                    g_mask[((size_t)b*144 + (c - 288))*HW + pix] = 1.f/(1.f + expf(-v));
                }
            }
        }
    }
}

// ---------------- modulated deformable conv, 4-way group split ----------------
// Grid: (256 pixel-tiles, BB, 4 quads). Block: 256 threads, 64 px, 4 groups
// accumulated in registers; partial result per quad to g_part.
__global__ __launch_bounds__(256) void dcn4_k()
{
    __shared__ float s_val[72][64];
    __shared__ float s_w[72][64];

    int p0 = blockIdx.x << 6;      // pixel base (half a row)
    int b  = blockIdx.y;
    int q  = blockIdx.z;           // group quad
    int t  = threadIdx.x;
    int o4 = (t & 15) << 2;        // 4 output channels
    int pb = (t >> 4) << 2;        // 4 pixels

    float accs[16];
#pragma unroll
    for (int i = 0; i < 16; i++) accs[i] = 0.f;

    const float* offb = g_off  + (size_t)b*288*HW;
    const float* mb   = g_mask + (size_t)b*144*HW;
    const float* xb   = g_xt   + (size_t)b*128*HW;

    for (int gi = 0; gi < 4; gi++) {
        int g = q*4 + gi;
        // weights: coalesced float4 copy from pre-transposed g_wt
        {
            const float4* src = (const float4*)(g_wt + (size_t)g*4608);
            float4* dst = (float4*)&s_w[0][0];
            for (int i = t; i < 1152; i += 256) dst[i] = src[i];
        }
        // sampling: 576 (k,pixel) tasks, 8 channels each, clamped unconditional loads
#pragma unroll
        for (int rep = 0; rep < 3; rep++) {
            int task = t + (rep << 8);
            if (task < 576) {
                int k   = task >> 6;
                int p   = task & 63;
                int pix = p0 + p;
                int y   = pix >> 7;
                int x   = pix & 127;
                int ch  = g*9 + k;
                float oy = offb[(size_t)(2*ch)    *HW + pix];
                float ox = offb[(size_t)(2*ch + 1)*HW + pix];
                float m  = mb  [(size_t)ch*HW + pix];
                float py = (float)(y + (k/3) - 1) + oy;
                float px = (float)(x + (k%3) - 1) + ox;
                float fy = floorf(py), fx = floorf(px);
                float wy = py - fy, wx = px - fx;
                int y0 = (int)fy,  x0 = (int)fx;
                int y1 = y0 + 1,   x1 = x0 + 1;
                float vy0 = ((unsigned)y0 < HH) ? 1.f : 0.f;
                float vy1 = ((unsigned)y1 < HH) ? 1.f : 0.f;
                float vx0 = ((unsigned)x0 < WW) ? 1.f : 0.f;
                float vx1 = ((unsigned)x1 < WW) ? 1.f : 0.f;
                int y0c = min(max(y0, 0), HH-1), y1c = min(max(y1, 0), HH-1);
                int x0c = min(max(x0, 0), WW-1), x1c = min(max(x1, 0), WW-1);
                float w00 = (1.f-wy)*(1.f-wx)*m*vy0*vx0;
                float w01 = (1.f-wy)*wx      *m*vy0*vx1;
                float w10 = wy*(1.f-wx)      *m*vy1*vx0;
                float w11 = wy*wx            *m*vy1*vx1;
                const float* gb = xb + (size_t)g*(HW*8);
                const float4* c00 = (const float4*)(gb + ((size_t)(y0c*WW + x0c) << 3));
                const float4* c01 = (const float4*)(gb + ((size_t)(y0c*WW + x1c) << 3));
                const float4* c10 = (const float4*)(gb + ((size_t)(y1c*WW + x0c) << 3));
                const float4* c11 = (const float4*)(gb + ((size_t)(y1c*WW + x1c) << 3));
                float4 a0 = c00[0], a1 = c00[1];
                float4 b0 = c01[0], b1 = c01[1];
                float4 d0 = c10[0], d1 = c10[1];
                float4 e0 = c11[0], e1 = c11[1];
                float lo0 = w00*a0.x + w01*b0.x + w10*d0.x + w11*e0.x;
                float lo1 = w00*a0.y + w01*b0.y + w10*d0.y + w11*e0.y;
                float lo2 = w00*a0.z + w01*b0.z + w10*d0.z + w11*e0.z;
                float lo3 = w00*a0.w + w01*b0.w + w10*d0.w + w11*e0.w;
                float hi0 = w00*a1.x + w01*b1.x + w10*d1.x + w11*e1.x;
                float hi1 = w00*a1.y + w01*b1.y + w10*d1.y + w11*e1.y;
                float hi2 = w00*a1.z + w01*b1.z + w10*d1.z + w11*e1.z;
                float hi3 = w00*a1.w + w01*b1.w + w10*d1.w + w11*e1.w;
                s_val[0*9 + k][p] = lo0;  s_val[1*9 + k][p] = lo1;
                s_val[2*9 + k][p] = lo2;  s_val[3*9 + k][p] = lo3;
                s_val[4*9 + k][p] = hi0;  s_val[5*9 + k][p] = hi1;
                s_val[6*9 + k][p] = hi2;  s_val[7*9 + k][p] = hi3;
            }
        }
        __syncthreads();

#pragma unroll 8
        for (int j = 0; j < 72; j++) {
            float4 wv = *(const float4*)&s_w[j][o4];
            float4 vv = *(const float4*)&s_val[j][pb];
            accs[0]  = fmaf(wv.x, vv.x, accs[0]);
            accs[1]  = fmaf(wv.x, vv.y, accs[1]);
            accs[2]  = fmaf(wv.x, vv.z, accs[2]);
            accs[3]  = fmaf(wv.x, vv.w, accs[3]);
            accs[4]  = fmaf(wv.y, vv.x, accs[4]);
            accs[5]  = fmaf(wv.y, vv.y, accs[5]);
            accs[6]  = fmaf(wv.y, vv.z, accs[6]);
            accs[7]  = fmaf(wv.y, vv.w, accs[7]);
            accs[8]  = fmaf(wv.z, vv.x, accs[8]);
            accs[9]  = fmaf(wv.z, vv.y, accs[9]);
            accs[10] = fmaf(wv.z, vv.z, accs[10]);
            accs[11] = fmaf(wv.z, vv.w, accs[11]);
            accs[12] = fmaf(wv.w, vv.x, accs[12]);
            accs[13] = fmaf(wv.w, vv.y, accs[13]);
            accs[14] = fmaf(wv.w, vv.z, accs[14]);
            accs[15] = fmaf(wv.w, vv.w, accs[15]);
        }
        __syncthreads();
    }

    float* pout = g_part + (((size_t)(q*BB + b))*64)*HW;
#pragma unroll
    for (int oi = 0; oi < 4; oi++)
#pragma unroll
        for (int pi = 0; pi < 4; pi++)
            pout[(size_t)(o4 + oi)*HW + p0 + pb + pi] = accs[oi*4 + pi];
}

// ---------------- reduce 4 quad-partials + bias ----------------
__global__ __launch_bounds__(256) void reduce_k(const float* __restrict__ bias,
                                                float* __restrict__ out)
{
    int i = blockIdx.x*256 + threadIdx.x;     // over BB*64*HW
    if (i >= BB*64*HW) return;
    int pix = i & (HW - 1);
    int c   = (i >> 14) & 63;
    int b   = i >> 20;
    float s = bias[c];
#pragma unroll
    for (int q = 0; q < 4; q++)
        s += g_part[(((size_t)(q*BB + b))*64 + c)*HW + pix];
    out[i] = s;
}

// ---------------- launch ----------------
extern "C" void kernel_launch(void* const* d_in, const int* in_sizes, int n_in,
                              void* d_out, int out_size)
{
    const float* x   = (const float*)d_in[0];
    const float* exf = (const float*)d_in[1];
    const float* f1  = (const float*)d_in[2];
    const float* f2  = (const float*)d_in[3];
    const float* w1  = (const float*)d_in[4];
    const float* b1  = (const float*)d_in[5];
    const float* w2  = (const float*)d_in[6];
    const float* b2  = (const float*)d_in[7];
    const float* w3  = (const float*)d_in[8];
    const float* b3  = (const float*)d_in[9];
    const float* w4  = (const float*)d_in[10];
    const float* b4  = (const float*)d_in[11];
    const float* dw  = (const float*)d_in[12];
    const float* db  = (const float*)d_in[13];
    float* out = (float*)d_out;

    float *p_ef, *p_h1, *p_h2;
    cudaGetSymbolAddress((void**)&p_ef, g_ef);
    cudaGetSymbolAddress((void**)&p_h1, g_h1);
    cudaGetSymbolAddress((void**)&p_h2, g_h2);

    concat_ef_k<<<(BB*196*HW + 255)/256, 256>>>(exf, f1, f2);
    transp_x_k <<<(BB*128*HW + 255)/256, 256>>>(x);
    transp_w_k <<<(16*72*64 + 255)/256, 256>>>(dw);

    conv3x3_k<0><<<dim3(4, 16, 8),  256>>>(p_ef, w1, b1, p_h1, 196, 64, nullptr, nullptr);
    conv3x3_k<0><<<dim3(4, 16, 8),  256>>>(p_h1, w2, b2, p_h2,  64, 64, nullptr, nullptr);
    conv3x3_k<0><<<dim3(4, 16, 8),  256>>>(p_h2, w3, b3, p_h1,  64, 64, nullptr, nullptr);
    conv3x3_k<1><<<dim3(4, 16, 54), 256>>>(p_h1, w4, b4, nullptr, 64, 432, f1, f2);

    dcn4_k<<<dim3(256, BB, 4), 256>>>();

    reduce_k<<<(BB*64*HW + 255)/256, 256>>>(db, out);
}

// round 7
// speedup vs baseline: 2.0874x; 1.7524x over previous
#include <cuda_runtime.h>
#include <cuda_bf16.h>
#include <math.h>
#include <stdint.h>

#define HH 128
#define WW 128
#define HW 16384
#define BB 2

// ==================== helpers ====================
__device__ __forceinline__ uint32_t smem_u32(const void* p) {
    uint32_t a;
    asm("{ .reg .u64 t; cvta.to.shared.u64 t, %1; cvt.u32.u64 %0, t; }" : "=r"(a) : "l"(p));
    return a;
}
__device__ __forceinline__ void ldsm_x4(uint32_t* r, uint32_t addr) {
    asm volatile("ldmatrix.sync.aligned.m8n8.x4.shared.b16 {%0,%1,%2,%3}, [%4];"
        : "=r"(r[0]), "=r"(r[1]), "=r"(r[2]), "=r"(r[3]) : "r"(addr));
}
__device__ __forceinline__ void mma_bf16(float* c, const uint32_t* a, const uint32_t* b) {
    asm volatile(
        "mma.sync.aligned.m16n8k16.row.col.f32.bf16.bf16.f32 "
        "{%0,%1,%2,%3}, {%4,%5,%6,%7}, {%8,%9}, {%0,%1,%2,%3};"
        : "+f"(c[0]), "+f"(c[1]), "+f"(c[2]), "+f"(c[3])
        : "r"(a[0]), "r"(a[1]), "r"(a[2]), "r"(a[3]), "r"(b[0]), "r"(b[1]));
}
__device__ __forceinline__ uint32_t pack_bf(float v) {
    __nv_bfloat16 h = __float2bfloat16(v);
    float hf = __bfloat162float(h);
    __nv_bfloat16 l = __float2bfloat16(v - hf);
    return (uint32_t)__bfloat16_as_ushort(h) | ((uint32_t)__bfloat16_as_ushort(l) << 16);
}

// ==================== scratch globals ====================
__device__ uint32_t g_in0 [BB*196*HW];   // packed bf16 hi | lo<<16
__device__ uint32_t g_h1  [BB*64*HW];
__device__ uint32_t g_h2  [BB*64*HW];
__device__ uint32_t g_h3  [BB*64*HW];
__device__ float    g_off [BB*288*HW];
__device__ float    g_mask[BB*144*HW];
__device__ float    g_xt  [BB*128*HW];
__device__ float    g_wt  [16*72*64];
__device__ float    g_part[4*BB*64*HW];
// weight tiles: [j][CoutP rows][72 cols] bf16, zero-padded (cols 64-71, invalid cin/cout)
__device__ __align__(16) uint16_t g_w1h[36*64*72],  g_w1l[36*64*72];
__device__ __align__(16) uint16_t g_w2h[9*64*72],   g_w2l[9*64*72];
__device__ __align__(16) uint16_t g_w3h[9*64*72],   g_w3l[9*64*72];
__device__ __align__(16) uint16_t g_w4h[9*448*72],  g_w4l[9*448*72];

// ==================== prep kernels ====================
__global__ __launch_bounds__(256) void pack_in0_k(
    const float* __restrict__ ef, const float* __restrict__ f1, const float* __restrict__ f2)
{
    int i = blockIdx.x*256 + threadIdx.x;
    if (i >= BB*196*HW) return;
    int pix = i % HW;
    int c = (i / HW) % 196;
    int b = i / (196*HW);
    float v;
    if (c < 192)      v = ef[((size_t)b*192 + c)*HW + pix];
    else if (c < 194) v = f1[((size_t)b*2 + (c-192))*HW + pix];
    else              v = f2[((size_t)b*2 + (c-194))*HW + pix];
    g_in0[i] = pack_bf(v);
}

__global__ __launch_bounds__(256) void wprep_k(
    const float* __restrict__ w, int Cin, int CoutR, int CoutP, int J,
    uint16_t* __restrict__ dh, uint16_t* __restrict__ dl)
{
    int idx = blockIdx.x*256 + threadIdx.x;
    if (idx >= J*CoutP*72) return;
    int col = idx % 72;
    int o   = (idx / 72) % CoutP;
    int j   = idx / (72*CoutP);
    int cc = j / 9, kk = j % 9;
    int cin = cc*64 + col;
    float v = (col < 64 && cin < Cin && o < CoutR) ? w[((size_t)o*Cin + cin)*9 + kk] : 0.f;
    __nv_bfloat16 h = __float2bfloat16(v);
    float hf = __bfloat162float(h);
    __nv_bfloat16 l = __float2bfloat16(v - hf);
    dh[idx] = __bfloat16_as_ushort(h);
    dl[idx] = __bfloat16_as_ushort(l);
}

__global__ __launch_bounds__(256) void transp_x_k(const float* __restrict__ x)
{
    int i = blockIdx.x*256 + threadIdx.x;
    if (i >= BB*128*HW) return;
    int cc = i & 7, rest = i >> 3;
    int pix = rest % HW, g = (rest / HW) % 16, b = rest / (16*HW);
    g_xt[i] = x[((size_t)(b*128 + g*8 + cc))*HW + pix];
}

__global__ __launch_bounds__(256) void transp_w_k(const float* __restrict__ w)
{
    int i = blockIdx.x*256 + threadIdx.x;
    if (i >= 16*72*64) return;
    int o = i & 63, j = (i >> 6) % 72, g = i / (72*64);
    g_wt[i] = w[(size_t)o*1152 + (g*8 + j/9)*9 + (j % 9)];
}

// ==================== mma.sync conv3x3 ====================
// CTA = one (b,row), M=128 px, N=64 cout chunk (blockIdx.y), K chunks of 64.
// 3-term bf16 split: D = Ah*Bh + Ah*Bl + Al*Bh, fp32 accumulate.
template<int CIN, int COUTP, int COUTR, int EPI>
__global__ __launch_bounds__(256, 1) void convmma_k(
    const uint32_t* __restrict__ in, const uint16_t* __restrict__ wh,
    const uint16_t* __restrict__ wl, const float* __restrict__ bias,
    uint32_t* __restrict__ outp,
    const float* __restrict__ flow1, const float* __restrict__ flow2)
{
    extern __shared__ char sm[];
    constexpr int CCH = (CIN + 63) / 64;
    constexpr int J   = CCH * 9;
    const int OFF_SCR = 0;          // 64*133*4 = 34048 B
    const int OFF_AH  = 34048;      // 128 rows * 144 B
    const int OFF_AL  = 52480;
    const int OFF_BH  = 70912;      // 64 rows * 144 B
    const int OFF_BL  = 80128;

    uint32_t sbase = smem_u32(sm);
    int t = threadIdx.x, lane = t & 31, wid = t >> 5;
    int tile = blockIdx.x;
    int b = tile >> 7, y = tile & 127;
    int nc = blockIdx.y;
    int warp_m = wid & 3, warp_n = wid >> 2;

    float acc[2][4][4];
#pragma unroll
    for (int i = 0; i < 2; i++)
#pragma unroll
        for (int j2 = 0; j2 < 4; j2++)
#pragma unroll
            for (int k2 = 0; k2 < 4; k2++) acc[i][j2][k2] = 0.f;

    uint32_t* scr = (uint32_t*)(sm + OFF_SCR);
    const uint32_t* inb = in + (size_t)b*CIN*HW;
    const int thc = t & 63, thp = t >> 6;
    const uint32_t scrb = (uint32_t)thc*133u;

    // ldmatrix base addresses (element offsets scaled later)
    const uint32_t aAH = sbase + OFF_AH, aAL = sbase + OFF_AL;
    const uint32_t aBH = sbase + OFF_BH, aBL = sbase + OFF_BL;
    const int arow = warp_m*32 + (lane & 15);
    const int aseg = lane >> 4;
    const int brow = warp_n*32 + (lane & 7) + ((lane >> 4) & 1)*8;
    const int bseg = (lane >> 3) & 1;

    for (int j = 0; j < J; j++) {
        int cc = j / 9, kk = j % 9, ky = kk / 3, kx = kk % 3;
        __syncthreads();                               // prior chunk consumed
        if (kx == 0) {
            int r = y + ky - 1;
            bool rok = (unsigned)r < (unsigned)HH;
            int cbase = cc * 64;
            for (int i = t; i < 64*128; i += 256) {
                int c = i >> 7, px = i & 127;
                uint32_t v = 0;
                if (rok && (cbase + c) < CIN) v = inb[(size_t)(cbase + c)*HW + r*WW + px];
                scr[c*133 + 1 + px] = v;
            }
            if (t < 64) { scr[t*133] = 0; scr[t*133 + 129] = 0; }
            __syncthreads();
        }
        // stage A: A[px][c] = scr[c][px + kx], split hi/lo, stride 72
        {
            uint16_t* ah = (uint16_t*)(sm + OFF_AH);
            uint16_t* al = (uint16_t*)(sm + OFF_AL);
            uint32_t sidx = scrb + thp + kx;
#pragma unroll
            for (int e = 0; e < 32; e++) {
                int px = thp + e*4;
                uint32_t wv = scr[sidx + e*4];
                ah[px*72 + thc] = (uint16_t)wv;
                al[px*72 + thc] = (uint16_t)(wv >> 16);
            }
        }
        // copy B slice (64 rows x 144B, linear)
        {
            const float4* shp = (const float4*)(wh + ((size_t)j*COUTP + nc*64)*72);
            const float4* slp = (const float4*)(wl + ((size_t)j*COUTP + nc*64)*72);
            float4* dhp = (float4*)(sm + OFF_BH);
            float4* dlp = (float4*)(sm + OFF_BL);
            for (int i = t; i < 576; i += 256) { dhp[i] = shp[i]; dlp[i] = slp[i]; }
        }
        __syncthreads();

        // mma over this K=64 chunk
#pragma unroll
        for (int ks = 0; ks < 4; ks++) {
            uint32_t a_h[2][4], a_l[2][4], b_h[2][4], b_l[2][4];
            uint32_t aoff = (uint32_t)(ks*16 + aseg*8) * 2;
            uint32_t boff = (uint32_t)(ks*16 + bseg*8) * 2;
            ldsm_x4(a_h[0], aAH + (uint32_t)(arow*72)*2 + aoff);
            ldsm_x4(a_h[1], aAH + (uint32_t)((arow+16)*72)*2 + aoff);
            ldsm_x4(a_l[0], aAL + (uint32_t)(arow*72)*2 + aoff);
            ldsm_x4(a_l[1], aAL + (uint32_t)((arow+16)*72)*2 + aoff);
            ldsm_x4(b_h[0], aBH + (uint32_t)(brow*72)*2 + boff);
            ldsm_x4(b_h[1], aBH + (uint32_t)((brow+16)*72)*2 + boff);
            ldsm_x4(b_l[0], aBL + (uint32_t)(brow*72)*2 + boff);
            ldsm_x4(b_l[1], aBL + (uint32_t)((brow+16)*72)*2 + boff);
#pragma unroll
            for (int mt = 0; mt < 2; mt++)
#pragma unroll
                for (int np = 0; np < 2; np++)
#pragma unroll
                    for (int sub = 0; sub < 2; sub++) {
                        int nt = np*2 + sub;
                        mma_bf16(acc[mt][nt], a_h[mt], &b_h[np][sub*2]);
                        mma_bf16(acc[mt][nt], a_h[mt], &b_l[np][sub*2]);
                        mma_bf16(acc[mt][nt], a_l[mt], &b_h[np][sub*2]);
                    }
        }
    }

    // epilogue
    int g = lane >> 2, tq = lane & 3;
#pragma unroll
    for (int mt = 0; mt < 2; mt++) {
#pragma unroll
        for (int nt = 0; nt < 4; nt++) {
#pragma unroll
            for (int rg = 0; rg < 4; rg++) {
                int px = warp_m*32 + mt*16 + g + ((rg >> 1) ? 8 : 0);
                int n  = warp_n*32 + nt*8 + tq*2 + (rg & 1);
                int c  = nc*64 + n;
                if (c >= COUTR) continue;
                int pix = y*WW + px;
                float v = acc[mt][nt][rg] + bias[c];
                if (EPI == 0) {
                    v = v >= 0.f ? v : 0.1f*v;
                    outp[((size_t)b*COUTR + c)*HW + pix] = pack_bf(v);
                } else {
                    if (c < 288) {
                        const float* fl = (c < 144) ? flow1 : flow2;
                        float add = fl[((size_t)b*2 + (1 - (c & 1)))*HW + pix];
                        g_off[((size_t)b*288 + c)*HW + pix] = 10.f*tanhf(v) + add;
                    } else {
                        g_mask[((size_t)b*144 + (c - 288))*HW + pix] = 1.f/(1.f + expf(-v));
                    }
                }
            }
        }
    }
}

// ==================== modulated deformable conv (fp32, as R3) ====================
__global__ __launch_bounds__(256) void dcn4_k()
{
    __shared__ float s_val[72][64];
    __shared__ float s_w[72][64];
    int p0 = blockIdx.x << 6, b = blockIdx.y, q = blockIdx.z;
    int t = threadIdx.x;
    int o4 = (t & 15) << 2, pb = (t >> 4) << 2;
    float accs[16];
#pragma unroll
    for (int i = 0; i < 16; i++) accs[i] = 0.f;
    const float* offb = g_off  + (size_t)b*288*HW;
    const float* mb   = g_mask + (size_t)b*144*HW;
    const float* xb   = g_xt   + (size_t)b*128*HW;

    for (int gi = 0; gi < 4; gi++) {
        int g = q*4 + gi;
        {
            const float4* src = (const float4*)(g_wt + (size_t)g*4608);
            float4* dst = (float4*)&s_w[0][0];
            for (int i = t; i < 1152; i += 256) dst[i] = src[i];
        }
#pragma unroll
        for (int rep = 0; rep < 3; rep++) {
            int task = t + (rep << 8);
            if (task < 576) {
                int k = task >> 6, p = task & 63;
                int pix = p0 + p, y = pix >> 7, x = pix & 127;
                int ch = g*9 + k;
                float oy = offb[(size_t)(2*ch)    *HW + pix];
                float ox = offb[(size_t)(2*ch + 1)*HW + pix];
                float m  = mb  [(size_t)ch*HW + pix];
                float py = (float)(y + (k/3) - 1) + oy;
                float px = (float)(x + (k%3) - 1) + ox;
                float fy = floorf(py), fx = floorf(px);
                float wy = py - fy, wx = px - fx;
                int y0 = (int)fy, x0 = (int)fx, y1 = y0 + 1, x1 = x0 + 1;
                float vy0 = ((unsigned)y0 < HH) ? 1.f : 0.f;
                float vy1 = ((unsigned)y1 < HH) ? 1.f : 0.f;
                float vx0 = ((unsigned)x0 < WW) ? 1.f : 0.f;
                float vx1 = ((unsigned)x1 < WW) ? 1.f : 0.f;
                int y0c = min(max(y0,0),HH-1), y1c = min(max(y1,0),HH-1);
                int x0c = min(max(x0,0),WW-1), x1c = min(max(x1,0),WW-1);
                float w00 = (1.f-wy)*(1.f-wx)*m*vy0*vx0;
                float w01 = (1.f-wy)*wx      *m*vy0*vx1;
                float w10 = wy*(1.f-wx)      *m*vy1*vx0;
                float w11 = wy*wx            *m*vy1*vx1;
                const float* gb = xb + (size_t)g*(HW*8);
                const float4* c00 = (const float4*)(gb + ((size_t)(y0c*WW + x0c) << 3));
                const float4* c01 = (const float4*)(gb + ((size_t)(y0c*WW + x1c) << 3));
                const float4* c10 = (const float4*)(gb + ((size_t)(y1c*WW + x0c) << 3));
                const float4* c11 = (const float4*)(gb + ((size_t)(y1c*WW + x1c) << 3));
                float4 a0 = c00[0], a1 = c00[1];
                float4 b0 = c01[0], b1 = c01[1];
                float4 d0 = c10[0], d1 = c10[1];
                float4 e0 = c11[0], e1 = c11[1];
                s_val[0*9+k][p] = w00*a0.x + w01*b0.x + w10*d0.x + w11*e0.x;
                s_val[1*9+k][p] = w00*a0.y + w01*b0.y + w10*d0.y + w11*e0.y;
                s_val[2*9+k][p] = w00*a0.z + w01*b0.z + w10*d0.z + w11*e0.z;
                s_val[3*9+k][p] = w00*a0.w + w01*b0.w + w10*d0.w + w11*e0.w;
                s_val[4*9+k][p] = w00*a1.x + w01*b1.x + w10*d1.x + w11*e1.x;
                s_val[5*9+k][p] = w00*a1.y + w01*b1.y + w10*d1.y + w11*e1.y;
                s_val[6*9+k][p] = w00*a1.z + w01*b1.z + w10*d1.z + w11*e1.z;
                s_val[7*9+k][p] = w00*a1.w + w01*b1.w + w10*d1.w + w11*e1.w;
            }
        }
        __syncthreads();

#pragma unroll 8
        for (int j = 0; j < 72; j++) {
            float4 wv = *(const float4*)&s_w[j][o4];
            float4 vv = *(const float4*)&s_val[j][pb];
            accs[0]  = fmaf(wv.x, vv.x, accs[0]);
            accs[1]  = fmaf(wv.x, vv.y, accs[1]);
            accs[2]  = fmaf(wv.x, vv.z, accs[2]);
            accs[3]  = fmaf(wv.x, vv.w, accs[3]);
            accs[4]  = fmaf(wv.y, vv.x, accs[4]);
            accs[5]  = fmaf(wv.y, vv.y, accs[5]);
            accs[6]  = fmaf(wv.y, vv.z, accs[6]);
            accs[7]  = fmaf(wv.y, vv.w, accs[7]);
            accs[8]  = fmaf(wv.z, vv.x, accs[8]);
            accs[9]  = fmaf(wv.z, vv.y, accs[9]);
            accs[10] = fmaf(wv.z, vv.z, accs[10]);
            accs[11] = fmaf(wv.z, vv.w, accs[11]);
            accs[12] = fmaf(wv.w, vv.x, accs[12]);
            accs[13] = fmaf(wv.w, vv.y, accs[13]);
            accs[14] = fmaf(wv.w, vv.z, accs[14]);
            accs[15] = fmaf(wv.w, vv.w, accs[15]);
        }
        __syncthreads();
    }

    float* pout = g_part + (((size_t)(q*BB + b))*64)*HW;
#pragma unroll
    for (int oi = 0; oi < 4; oi++)
#pragma unroll
        for (int pi = 0; pi < 4; pi++)
            pout[(size_t)(o4 + oi)*HW + p0 + pb + pi] = accs[oi*4 + pi];
}

__global__ __launch_bounds__(256) void reduce_k(const float* __restrict__ bias,
                                                float* __restrict__ out)
{
    int i = blockIdx.x*256 + threadIdx.x;
    if (i >= BB*64*HW) return;
    int pix = i & (HW - 1);
    int c   = (i >> 14) & 63;
    int b   = i >> 20;
    float s = bias[c];
#pragma unroll
    for (int q = 0; q < 4; q++)
        s += g_part[(((size_t)(q*BB + b))*64 + c)*HW + pix];
    out[i] = s;
}

// ==================== launch ====================
extern "C" void kernel_launch(void* const* d_in, const int* in_sizes, int n_in,
                              void* d_out, int out_size)
{
    const float* x   = (const float*)d_in[0];
    const float* exf = (const float*)d_in[1];
    const float* f1  = (const float*)d_in[2];
    const float* f2  = (const float*)d_in[3];
    const float* w1  = (const float*)d_in[4];
    const float* b1  = (const float*)d_in[5];
    const float* w2  = (const float*)d_in[6];
    const float* b2  = (const float*)d_in[7];
    const float* w3  = (const float*)d_in[8];
    const float* b3  = (const float*)d_in[9];
    const float* w4  = (const float*)d_in[10];
    const float* b4  = (const float*)d_in[11];
    const float* dw  = (const float*)d_in[12];
    const float* db  = (const float*)d_in[13];
    float* out = (float*)d_out;

    uint32_t *p_in0, *p_h1, *p_h2, *p_h3;
    uint16_t *p_w1h, *p_w1l, *p_w2h, *p_w2l, *p_w3h, *p_w3l, *p_w4h, *p_w4l;
    cudaGetSymbolAddress((void**)&p_in0, g_in0);
    cudaGetSymbolAddress((void**)&p_h1,  g_h1);
    cudaGetSymbolAddress((void**)&p_h2,  g_h2);
    cudaGetSymbolAddress((void**)&p_h3,  g_h3);
    cudaGetSymbolAddress((void**)&p_w1h, g_w1h);  cudaGetSymbolAddress((void**)&p_w1l, g_w1l);
    cudaGetSymbolAddress((void**)&p_w2h, g_w2h);  cudaGetSymbolAddress((void**)&p_w2l, g_w2l);
    cudaGetSymbolAddress((void**)&p_w3h, g_w3h);  cudaGetSymbolAddress((void**)&p_w3l, g_w3l);
    cudaGetSymbolAddress((void**)&p_w4h, g_w4h);  cudaGetSymbolAddress((void**)&p_w4l, g_w4l);

    const int SMTOT = 89344;
    cudaFuncSetAttribute(convmma_k<196,64,64,0>,  cudaFuncAttributeMaxDynamicSharedMemorySize, SMTOT);
    cudaFuncSetAttribute(convmma_k<64,64,64,0>,   cudaFuncAttributeMaxDynamicSharedMemorySize, SMTOT);
    cudaFuncSetAttribute(convmma_k<64,448,432,1>, cudaFuncAttributeMaxDynamicSharedMemorySize, SMTOT);

    pack_in0_k<<<(BB*196*HW + 255)/256, 256>>>(exf, f1, f2);
    transp_x_k<<<(BB*128*HW + 255)/256, 256>>>(x);
    transp_w_k<<<(16*72*64 + 255)/256, 256>>>(dw);
    wprep_k<<<(36*64*72  + 255)/256, 256>>>(w1, 196, 64, 64, 36, p_w1h, p_w1l);
    wprep_k<<<(9*64*72   + 255)/256, 256>>>(w2,  64, 64, 64,  9, p_w2h, p_w2l);
    wprep_k<<<(9*64*72   + 255)/256, 256>>>(w3,  64, 64, 64,  9, p_w3h, p_w3l);
    wprep_k<<<(9*448*72  + 255)/256, 256>>>(w4,  64, 432, 448, 9, p_w4h, p_w4l);

    convmma_k<196,64,64,0> <<<dim3(256,1), 256, SMTOT>>>(p_in0, p_w1h, p_w1l, b1, p_h1, nullptr, nullptr);
    convmma_k<64,64,64,0>  <<<dim3(256,1), 256, SMTOT>>>(p_h1,  p_w2h, p_w2l, b2, p_h2, nullptr, nullptr);
    convmma_k<64,64,64,0>  <<<dim3(256,1), 256, SMTOT>>>(p_h2,  p_w3h, p_w3l, b3, p_h3, nullptr, nullptr);
    convmma_k<64,448,432,1><<<dim3(256,7), 256, SMTOT>>>(p_h3,  p_w4h, p_w4l, b4, nullptr, f1, f2);

    dcn4_k<<<dim3(256, BB, 4), 256>>>();
    reduce_k<<<(BB*64*HW + 255)/256, 256>>>(db, out);
}

// round 8
// speedup vs baseline: 2.2741x; 1.0894x over previous
#include <cuda_runtime.h>
#include <cuda_bf16.h>
#include <math.h>
#include <stdint.h>

#define HH 128
#define WW 128
#define HW 16384
#define BB 2

// ==================== helpers ====================
__device__ __forceinline__ uint32_t smem_u32(const void* p) {
    uint32_t a;
    asm("{ .reg .u64 t; cvta.to.shared.u64 t, %1; cvt.u32.u64 %0, t; }" : "=r"(a) : "l"(p));
    return a;
}
__device__ __forceinline__ void ldsm_x4(uint32_t* r, uint32_t addr) {
    asm volatile("ldmatrix.sync.aligned.m8n8.x4.shared.b16 {%0,%1,%2,%3}, [%4];"
        : "=r"(r[0]), "=r"(r[1]), "=r"(r[2]), "=r"(r[3]) : "r"(addr));
}
__device__ __forceinline__ void mma_bf16(float* c, const uint32_t* a, const uint32_t* b) {
    asm volatile(
        "mma.sync.aligned.m16n8k16.row.col.f32.bf16.bf16.f32 "
        "{%0,%1,%2,%3}, {%4,%5,%6,%7}, {%8,%9}, {%0,%1,%2,%3};"
        : "+f"(c[0]), "+f"(c[1]), "+f"(c[2]), "+f"(c[3])
        : "r"(a[0]), "r"(a[1]), "r"(a[2]), "r"(a[3]), "r"(b[0]), "r"(b[1]));
}
__device__ __forceinline__ uint32_t pack_bf(float v) {
    __nv_bfloat16 h = __float2bfloat16(v);
    float hf = __bfloat162float(h);
    __nv_bfloat16 l = __float2bfloat16(v - hf);
    return (uint32_t)__bfloat16_as_ushort(h) | ((uint32_t)__bfloat16_as_ushort(l) << 16);
}

// ==================== scratch globals ====================
// activations channels-last, packed bf16 hi|lo<<16: [b][cc][pix][64]
__device__ uint32_t g_in0 [BB*4*HW*64];
__device__ uint32_t g_h1  [BB*HW*64];
__device__ uint32_t g_h2  [BB*HW*64];
__device__ uint32_t g_h3  [BB*HW*64];
__device__ float    g_off [BB*288*HW];
__device__ float    g_mask[BB*144*HW];
__device__ float    g_xt  [BB*128*HW];
__device__ float    g_wt  [16*72*64];
__device__ float    g_part[4*BB*64*HW];
// weight tiles: [j][CoutP rows][72 cols] bf16, zero-padded
__device__ __align__(16) uint16_t g_w1h[36*64*72],  g_w1l[36*64*72];
__device__ __align__(16) uint16_t g_w2h[9*64*72],   g_w2l[9*64*72];
__device__ __align__(16) uint16_t g_w3h[9*64*72],   g_w3l[9*64*72];
__device__ __align__(16) uint16_t g_w4h[9*448*72],  g_w4l[9*448*72];

// ==================== prep kernels ====================
// concat + pack + transpose to channels-last, smem-tiled (both sides coalesced)
__global__ __launch_bounds__(256) void pack_in0_k(
    const float* __restrict__ ef, const float* __restrict__ f1, const float* __restrict__ f2)
{
    __shared__ uint32_t S[64*65];
    int cc = blockIdx.y, b = blockIdx.z;
    int pix0 = blockIdx.x * 64;
    int t = threadIdx.x;
    for (int i = t; i < 4096; i += 256) {
        int ch = i >> 6, px = i & 63;
        int g = cc*64 + ch;
        float v = 0.f;
        if (g < 192)      v = ef[((size_t)b*192 + g)*HW + pix0 + px];
        else if (g < 194) v = f1[((size_t)b*2 + (g-192))*HW + pix0 + px];
        else if (g < 196) v = f2[((size_t)b*2 + (g-194))*HW + pix0 + px];
        S[ch*65 + px] = pack_bf(v);
    }
    __syncthreads();
    for (int i = t; i < 4096; i += 256) {
        int px = i >> 6, ch = i & 63;
        g_in0[(((size_t)b*4 + cc)*HW + pix0 + px)*64 + ch] = S[ch*65 + px];
    }
}

__global__ __launch_bounds__(256) void wprep_k(
    const float* __restrict__ w, int Cin, int CoutR, int CoutP, int J,
    uint16_t* __restrict__ dh, uint16_t* __restrict__ dl)
{
    int idx = blockIdx.x*256 + threadIdx.x;
    if (idx >= J*CoutP*72) return;
    int col = idx % 72;
    int o   = (idx / 72) % CoutP;
    int j   = idx / (72*CoutP);
    int cc = j / 9, kk = j % 9;
    int cin = cc*64 + col;
    float v = (col < 64 && cin < Cin && o < CoutR) ? w[((size_t)o*Cin + cin)*9 + kk] : 0.f;
    __nv_bfloat16 h = __float2bfloat16(v);
    float hf = __bfloat162float(h);
    __nv_bfloat16 l = __float2bfloat16(v - hf);
    dh[idx] = __bfloat16_as_ushort(h);
    dl[idx] = __bfloat16_as_ushort(l);
}

// x -> [b][g][pix][8] channels-last, smem-tiled
__global__ __launch_bounds__(256) void transp_x_k(const float* __restrict__ x)
{
    __shared__ float S[8*257];
    int g = blockIdx.y, b = blockIdx.z;
    int pix0 = blockIdx.x * 256;
    int t = threadIdx.x;
    for (int i = t; i < 2048; i += 256) {
        int ch = i >> 8, px = i & 255;
        S[ch*257 + px] = x[((size_t)(b*128 + g*8 + ch))*HW + pix0 + px];
    }
    __syncthreads();
    for (int i = t; i < 2048; i += 256) {
        int px = i >> 3, ch = i & 7;
        g_xt[(((size_t)(b*16 + g))*HW + pix0 + px)*8 + ch] = S[ch*257 + px];
    }
}

__global__ __launch_bounds__(256) void transp_w_k(const float* __restrict__ w)
{
    int i = blockIdx.x*256 + threadIdx.x;
    if (i >= 16*72*64) return;
    int o = i & 63, j = (i >> 6) % 72, g = i / (72*64);
    g_wt[i] = w[(size_t)o*1152 + (g*8 + j/9)*9 + (j % 9)];
}

// ==================== mma.sync conv3x3 (direct-RT A) ====================
// CTA = (b, y, half-row): M=64 px, N=64 cout chunk (blockIdx.y), K = Cin*9 in 64-chunks.
// RT: halo'd channels-last row tile, hi/lo planes, 66 rows x 144B; A for (kx) = RT + kx rows.
// 3-term bf16 split: D = Ah*Bh + Ah*Bl + Al*Bh, fp32 accumulate.
template<int CIN, int COUTP, int COUTR, int EPI>
__global__ __launch_bounds__(256) void convmma_k(
    const uint32_t* __restrict__ in, const uint16_t* __restrict__ wh,
    const uint16_t* __restrict__ wl, const float* __restrict__ bias,
    uint32_t* __restrict__ outp,
    const float* __restrict__ flow1, const float* __restrict__ flow2)
{
    extern __shared__ char sm[];
    constexpr int CCH = (CIN + 63) / 64;
    const int OFF_RTH = 0;                 // 66*144 = 9504
    const int OFF_RTL = 9504;
    const int OFF_B   = 19008;             // 3 kx * (BH 9216 + BL 9216) = 55296

    uint32_t sbase = smem_u32(sm);
    int t = threadIdx.x, lane = t & 31, wid = t >> 5;
    int bx = blockIdx.x;
    int b = bx >> 8;
    int idx = bx & 255;
    int y = idx >> 1, x0 = (idx & 1) * 64;
    int nc = blockIdx.y;
    int warp_m = wid & 3, warp_n = wid >> 2;

    float acc[4][4];
#pragma unroll
    for (int i = 0; i < 4; i++)
#pragma unroll
        for (int j2 = 0; j2 < 4; j2++) acc[i][j2] = 0.f;

    const uint32_t aH_row = sbase + OFF_RTH + (uint32_t)(warp_m*16 + (lane & 15))*144u;
    const uint32_t aL_row = sbase + OFF_RTL + (uint32_t)(warp_m*16 + (lane & 15))*144u;
    const int aseg = lane >> 4;
    const uint32_t brq = (uint32_t)(warp_n*32 + (lane & 7) + ((lane >> 4) & 1)*8)*144u;
    const int bseg = (lane >> 3) & 1;

    for (int cc = 0; cc < CCH; cc++) {
        const uint32_t* img = in + (((size_t)b*CCH + cc)*HW)*64;
        for (int ky = 0; ky < 3; ky++) {
            int r = y + ky - 1;
            if ((unsigned)r >= (unsigned)HH) continue;
            __syncthreads();                 // prior MMAs done before RT/B overwrite
            // RT copy (66 halo rows, hi/lo split via byte_perm)
            {
                const float4* srow = (const float4*)(img + (size_t)r*WW*64);
                for (int i = t; i < 66*16; i += 256) {
                    int p = i >> 4, f = i & 15;
                    int x = x0 + p - 1;
                    float4 v = make_float4(0.f, 0.f, 0.f, 0.f);
                    if ((unsigned)x < (unsigned)WW) v = srow[x*16 + f];
                    uint32_t u0 = __float_as_uint(v.x), u1 = __float_as_uint(v.y);
                    uint32_t u2 = __float_as_uint(v.z), u3 = __float_as_uint(v.w);
                    uint2 hp = { __byte_perm(u0, u1, 0x5410), __byte_perm(u2, u3, 0x5410) };
                    uint2 lp = { __byte_perm(u0, u1, 0x7632), __byte_perm(u2, u3, 0x7632) };
                    *(uint2*)(sm + OFF_RTH + p*144 + f*8) = hp;
                    *(uint2*)(sm + OFF_RTL + p*144 + f*8) = lp;
                }
            }
            // B copy: 3 kx tiles (hi+lo) for this (cc,ky)
            {
                int j0 = cc*9 + ky*3;
#pragma unroll
                for (int kx = 0; kx < 3; kx++) {
                    const float4* shp = (const float4*)(wh + ((size_t)(j0+kx)*COUTP + nc*64)*72);
                    const float4* slp = (const float4*)(wl + ((size_t)(j0+kx)*COUTP + nc*64)*72);
                    float4* dhp = (float4*)(sm + OFF_B + kx*18432);
                    float4* dlp = (float4*)(sm + OFF_B + kx*18432 + 9216);
                    for (int i = t; i < 576; i += 256) { dhp[i] = shp[i]; dlp[i] = slp[i]; }
                }
            }
            __syncthreads();

#pragma unroll
            for (int kx = 0; kx < 3; kx++) {
                uint32_t aoff = (uint32_t)kx * 144u;
                uint32_t bH = sbase + OFF_B + kx*18432 + brq;
                uint32_t bL = bH + 9216;
#pragma unroll
                for (int ks = 0; ks < 4; ks++) {
                    uint32_t ka = (uint32_t)(ks*16 + aseg*8)*2;
                    uint32_t kb = (uint32_t)(ks*16 + bseg*8)*2;
                    uint32_t a_h[4], a_l[4], b_h[2][4], b_l[2][4];
                    ldsm_x4(a_h, aH_row + aoff + ka);
                    ldsm_x4(a_l, aL_row + aoff + ka);
                    ldsm_x4(b_h[0], bH + kb);
                    ldsm_x4(b_h[1], bH + 16*144 + kb);
                    ldsm_x4(b_l[0], bL + kb);
                    ldsm_x4(b_l[1], bL + 16*144 + kb);
#pragma unroll
                    for (int np = 0; np < 2; np++)
#pragma unroll
                        for (int sub = 0; sub < 2; sub++) {
                            int nt = np*2 + sub;
                            mma_bf16(acc[nt], a_h, &b_h[np][sub*2]);
                            mma_bf16(acc[nt], a_h, &b_l[np][sub*2]);
                            mma_bf16(acc[nt], a_l, &b_h[np][sub*2]);
                        }
                }
            }
        }
    }

    __syncthreads();    // all ldsm done before OT overwrites RT
    int g = lane >> 2, tq = lane & 3;
    if (EPI == 0) {
        uint32_t* OT = (uint32_t*)sm;       // [64 px][68] packed
#pragma unroll
        for (int nt = 0; nt < 4; nt++) {
#pragma unroll
            for (int rg = 0; rg < 4; rg++) {
                int px = warp_m*16 + g + ((rg >> 1) ? 8 : 0);
                int c  = warp_n*32 + nt*8 + tq*2 + (rg & 1);
                float v = acc[nt][rg] + bias[c];
                v = v >= 0.f ? v : 0.1f*v;
                OT[px*68 + c] = pack_bf(v);
            }
        }
        __syncthreads();
        for (int i = t; i < 1024; i += 256) {
            int p = i >> 4, f = i & 15;
            ((float4*)outp)[(((size_t)b*HW) + y*WW + x0 + p)*16 + f] =
                *(const float4*)(sm + p*272 + f*16);
        }
    } else {
#pragma unroll
        for (int nt = 0; nt < 4; nt++) {
#pragma unroll
            for (int rg = 0; rg < 4; rg++) {
                int px = warp_m*16 + g + ((rg >> 1) ? 8 : 0);
                int n  = warp_n*32 + nt*8 + tq*2 + (rg & 1);
                int c  = nc*64 + n;
                if (c >= COUTR) continue;
                int pix = y*WW + x0 + px;
                float v = acc[nt][rg] + bias[c];
                if (c < 288) {
                    const float* fl = (c < 144) ? flow1 : flow2;
                    float add = fl[((size_t)b*2 + (1 - (c & 1)))*HW + pix];
                    g_off[((size_t)b*288 + c)*HW + pix] = 10.f*tanhf(v) + add;
                } else {
                    g_mask[((size_t)b*144 + (c - 288))*HW + pix] = 1.f/(1.f + expf(-v));
                }
            }
        }
    }
}

// ==================== modulated deformable conv (fp32, unchanged) ====================
__global__ __launch_bounds__(256) void dcn4_k()
{
    __shared__ float s_val[72][64];
    __shared__ float s_w[72][64];
    int p0 = blockIdx.x << 6, b = blockIdx.y, q = blockIdx.z;
    int t = threadIdx.x;
    int o4 = (t & 15) << 2, pb = (t >> 4) << 2;
    float accs[16];
#pragma unroll
    for (int i = 0; i < 16; i++) accs[i] = 0.f;
    const float* offb = g_off  + (size_t)b*288*HW;
    const float* mb   = g_mask + (size_t)b*144*HW;
    const float* xb   = g_xt   + (size_t)b*128*HW;

    for (int gi = 0; gi < 4; gi++) {
        int g = q*4 + gi;
        {
            const float4* src = (const float4*)(g_wt + (size_t)g*4608);
            float4* dst = (float4*)&s_w[0][0];
            for (int i = t; i < 1152; i += 256) dst[i] = src[i];
        }
#pragma unroll
        for (int rep = 0; rep < 3; rep++) {
            int task = t + (rep << 8);
            if (task < 576) {
                int k = task >> 6, p = task & 63;
                int pix = p0 + p, y = pix >> 7, x = pix & 127;
                int ch = g*9 + k;
                float oy = offb[(size_t)(2*ch)    *HW + pix];
                float ox = offb[(size_t)(2*ch + 1)*HW + pix];
                float m  = mb  [(size_t)ch*HW + pix];
                float py = (float)(y + (k/3) - 1) + oy;
                float px = (float)(x + (k%3) - 1) + ox;
                float fy = floorf(py), fx = floorf(px);
                float wy = py - fy, wx = px - fx;
                int y0 = (int)fy, x0 = (int)fx, y1 = y0 + 1, x1 = x0 + 1;
                float vy0 = ((unsigned)y0 < HH) ? 1.f : 0.f;
                float vy1 = ((unsigned)y1 < HH) ? 1.f : 0.f;
                float vx0 = ((unsigned)x0 < WW) ? 1.f : 0.f;
                float vx1 = ((unsigned)x1 < WW) ? 1.f : 0.f;
                int y0c = min(max(y0,0),HH-1), y1c = min(max(y1,0),HH-1);
                int x0c = min(max(x0,0),WW-1), x1c = min(max(x1,0),WW-1);
                float w00 = (1.f-wy)*(1.f-wx)*m*vy0*vx0;
                float w01 = (1.f-wy)*wx      *m*vy0*vx1;
                float w10 = wy*(1.f-wx)      *m*vy1*vx0;
                float w11 = wy*wx            *m*vy1*vx1;
                const float* gb = xb + (size_t)g*(HW*8);
                const float4* c00 = (const float4*)(gb + ((size_t)(y0c*WW + x0c) << 3));
                const float4* c01 = (const float4*)(gb + ((size_t)(y0c*WW + x1c) << 3));
                const float4* c10 = (const float4*)(gb + ((size_t)(y1c*WW + x0c) << 3));
                const float4* c11 = (const float4*)(gb + ((size_t)(y1c*WW + x1c) << 3));
                float4 a0 = c00[0], a1 = c00[1];
                float4 b0 = c01[0], b1 = c01[1];
                float4 d0 = c10[0], d1 = c10[1];
                float4 e0 = c11[0], e1 = c11[1];
                s_val[0*9+k][p] = w00*a0.x + w01*b0.x + w10*d0.x + w11*e0.x;
                s_val[1*9+k][p] = w00*a0.y + w01*b0.y + w10*d0.y + w11*e0.y;
                s_val[2*9+k][p] = w00*a0.z + w01*b0.z + w10*d0.z + w11*e0.z;
                s_val[3*9+k][p] = w00*a0.w + w01*b0.w + w10*d0.w + w11*e0.w;
                s_val[4*9+k][p] = w00*a1.x + w01*b1.x + w10*d1.x + w11*e1.x;
                s_val[5*9+k][p] = w00*a1.y + w01*b1.y + w10*d1.y + w11*e1.y;
                s_val[6*9+k][p] = w00*a1.z + w01*b1.z + w10*d1.z + w11*e1.z;
                s_val[7*9+k][p] = w00*a1.w + w01*b1.w + w10*d1.w + w11*e1.w;
            }
        }
        __syncthreads();

#pragma unroll 8
        for (int j = 0; j < 72; j++) {
            float4 wv = *(const float4*)&s_w[j][o4];
            float4 vv = *(const float4*)&s_val[j][pb];
            accs[0]  = fmaf(wv.x, vv.x, accs[0]);
            accs[1]  = fmaf(wv.x, vv.y, accs[1]);
            accs[2]  = fmaf(wv.x, vv.z, accs[2]);
            accs[3]  = fmaf(wv.x, vv.w, accs[3]);
            accs[4]  = fmaf(wv.y, vv.x, accs[4]);
            accs[5]  = fmaf(wv.y, vv.y, accs[5]);
            accs[6]  = fmaf(wv.y, vv.z, accs[6]);
            accs[7]  = fmaf(wv.y, vv.w, accs[7]);
            accs[8]  = fmaf(wv.z, vv.x, accs[8]);
            accs[9]  = fmaf(wv.z, vv.y, accs[9]);
            accs[10] = fmaf(wv.z, vv.z, accs[10]);
            accs[11] = fmaf(wv.z, vv.w, accs[11]);
            accs[12] = fmaf(wv.w, vv.x, accs[12]);
            accs[13] = fmaf(wv.w, vv.y, accs[13]);
            accs[14] = fmaf(wv.w, vv.z, accs[14]);
            accs[15] = fmaf(wv.w, vv.w, accs[15]);
        }
        __syncthreads();
    }

    float* pout = g_part + (((size_t)(q*BB + b))*64)*HW;
#pragma unroll
    for (int oi = 0; oi < 4; oi++)
#pragma unroll
        for (int pi = 0; pi < 4; pi++)
            pout[(size_t)(o4 + oi)*HW + p0 + pb + pi] = accs[oi*4 + pi];
}

__global__ __launch_bounds__(256) void reduce_k(const float* __restrict__ bias,
                                                float* __restrict__ out)
{
    int i = blockIdx.x*256 + threadIdx.x;
    if (i >= BB*64*HW) return;
    int pix = i & (HW - 1);
    int c   = (i >> 14) & 63;
    int b   = i >> 20;
    float s = bias[c];
#pragma unroll
    for (int q = 0; q < 4; q++)
        s += g_part[(((size_t)(q*BB + b))*64 + c)*HW + pix];
    out[i] = s;
}

// ==================== launch ====================
extern "C" void kernel_launch(void* const* d_in, const int* in_sizes, int n_in,
                              void* d_out, int out_size)
{
    const float* x   = (const float*)d_in[0];
    const float* exf = (const float*)d_in[1];
    const float* f1  = (const float*)d_in[2];
    const float* f2  = (const float*)d_in[3];
    const float* w1  = (const float*)d_in[4];
    const float* b1  = (const float*)d_in[5];
    const float* w2  = (const float*)d_in[6];
    const float* b2  = (const float*)d_in[7];
    const float* w3  = (const float*)d_in[8];
    const float* b3  = (const float*)d_in[9];
    const float* w4  = (const float*)d_in[10];
    const float* b4  = (const float*)d_in[11];
    const float* dw  = (const float*)d_in[12];
    const float* db  = (const float*)d_in[13];
    float* out = (float*)d_out;

    uint32_t *p_in0, *p_h1, *p_h2, *p_h3;
    uint16_t *p_w1h, *p_w1l, *p_w2h, *p_w2l, *p_w3h, *p_w3l, *p_w4h, *p_w4l;
    cudaGetSymbolAddress((void**)&p_in0, g_in0);
    cudaGetSymbolAddress((void**)&p_h1,  g_h1);
    cudaGetSymbolAddress((void**)&p_h2,  g_h2);
    cudaGetSymbolAddress((void**)&p_h3,  g_h3);
    cudaGetSymbolAddress((void**)&p_w1h, g_w1h);  cudaGetSymbolAddress((void**)&p_w1l, g_w1l);
    cudaGetSymbolAddress((void**)&p_w2h, g_w2h);  cudaGetSymbolAddress((void**)&p_w2l, g_w2l);
    cudaGetSymbolAddress((void**)&p_w3h, g_w3h);  cudaGetSymbolAddress((void**)&p_w3l, g_w3l);
    cudaGetSymbolAddress((void**)&p_w4h, g_w4h);  cudaGetSymbolAddress((void**)&p_w4l, g_w4l);

    const int SMTOT = 19008 + 3*18432;   // 74304
    cudaFuncSetAttribute(convmma_k<196,64,64,0>,  cudaFuncAttributeMaxDynamicSharedMemorySize, SMTOT);
    cudaFuncSetAttribute(convmma_k<64,64,64,0>,   cudaFuncAttributeMaxDynamicSharedMemorySize, SMTOT);
    cudaFuncSetAttribute(convmma_k<64,448,432,1>, cudaFuncAttributeMaxDynamicSharedMemorySize, SMTOT);

    pack_in0_k<<<dim3(HW/64, 4, BB), 256>>>(exf, f1, f2);
    transp_x_k<<<dim3(HW/256, 16, BB), 256>>>(x);
    transp_w_k<<<(16*72*64 + 255)/256, 256>>>(dw);
    wprep_k<<<(36*64*72  + 255)/256, 256>>>(w1, 196, 64, 64, 36, p_w1h, p_w1l);
    wprep_k<<<(9*64*72   + 255)/256, 256>>>(w2,  64, 64, 64,  9, p_w2h, p_w2l);
    wprep_k<<<(9*64*72   + 255)/256, 256>>>(w3,  64, 64, 64,  9, p_w3h, p_w3l);
    wprep_k<<<(9*448*72  + 255)/256, 256>>>(w4,  64, 432, 448, 9, p_w4h, p_w4l);

    convmma_k<196,64,64,0> <<<dim3(BB*256, 1), 256, SMTOT>>>(p_in0, p_w1h, p_w1l, b1, p_h1, nullptr, nullptr);
    convmma_k<64,64,64,0>  <<<dim3(BB*256, 1), 256, SMTOT>>>(p_h1,  p_w2h, p_w2l, b2, p_h2, nullptr, nullptr);
    convmma_k<64,64,64,0>  <<<dim3(BB*256, 1), 256, SMTOT>>>(p_h2,  p_w3h, p_w3l, b3, p_h3, nullptr, nullptr);
    convmma_k<64,448,432,1><<<dim3(BB*256, 7), 256, SMTOT>>>(p_h3,  p_w4h, p_w4l, b4, nullptr, f1, f2);

    dcn4_k<<<dim3(256, BB, 4), 256>>>();
    reduce_k<<<(BB*64*HW + 255)/256, 256>>>(db, out);
}